// round 10
// baseline (speedup 1.0000x reference)
#include <cuda_runtime.h>
#include <cuda_bf16.h>
#include <cstdint>

// ============================================================================
// Problem constants
// ============================================================================
#define B_DIM   256
#define T_DIM   2048
#define K_DIM   64
#define H_DIM   128
#define TILE_T  32
#define N_TILES (T_DIM / TILE_T)   // 64

// Scan: y_t = 0.9*y_{t-1} - 1.25*th_{t-1} + g_t, th = tanh(y), spk = .5th+.5
// g = 2.5*ff - 1.5  (2.5 folded into W, bias' = 2.5b - 1.5)

// ============================================================================
// SMEM layout (bytes) — double buffers, 70656 total (2 CTAs/SM easily)
//   [0, 18432)       x ring: 2 slots x 9216 (hi 4608 + lo 4608), 32x144B rows
//   [18432, 36864)   W_lo persistent (128 x 144 B)
//   [36864, 70656)   ff ring: 2 slots x 16896 ([t][h] stride 132 floats)
//   W_hi (init only) aliases ff region at 36864.
// ============================================================================
#define WSTR      72
#define ROWB      144
#define XBUF(s)   ((s) * 9216)
#define SMEM_W_LO 18432
#define SMEM_FF   36864
#define FFB(s)    (SMEM_FF + (s) * 16896)
#define FF_STR    132
#define SMEM_W_HI 36864
#define SMEM_TOTAL 70656

// ============================================================================
// Helpers
// ============================================================================
__device__ __forceinline__ uint32_t smem_to_u32(const void* p) {
    uint32_t a;
    asm("{ .reg .u64 t; cvta.to.shared.u64 t, %1; cvt.u32.u64 %0, t; }"
        : "=r"(a) : "l"(p));
    return a;
}
__device__ __forceinline__ float tanhf_approx(float x) {
    float y; asm("tanh.approx.f32 %0, %1;" : "=f"(y) : "f"(x)); return y;
}
__device__ __forceinline__ void ldm_x4(uint32_t* r, uint32_t addr) {
    asm volatile("ldmatrix.sync.aligned.m8n8.x4.shared.b16 {%0,%1,%2,%3}, [%4];"
        : "=r"(r[0]), "=r"(r[1]), "=r"(r[2]), "=r"(r[3]) : "r"(addr));
}
__device__ __forceinline__ void mma_bf16(float* d, const uint32_t* a, const uint32_t* b) {
    asm volatile(
        "mma.sync.aligned.m16n8k16.row.col.f32.bf16.bf16.f32 "
        "{%0,%1,%2,%3},{%4,%5,%6,%7},{%8,%9},{%0,%1,%2,%3};"
        : "+f"(d[0]), "+f"(d[1]), "+f"(d[2]), "+f"(d[3])
        : "r"(a[0]), "r"(a[1]), "r"(a[2]), "r"(a[3]), "r"(b[0]), "r"(b[1]));
}
__device__ __forceinline__ uint32_t pack_bf16(__nv_bfloat16 a, __nv_bfloat16 b) {
    return ((uint32_t)__bfloat16_as_ushort(b) << 16) | __bfloat16_as_ushort(a);
}
__device__ __forceinline__ void cvt_pack(float4 v, uint2& hi, uint2& lo) {
    __nv_bfloat16 h0 = __float2bfloat16(v.x);
    __nv_bfloat16 h1 = __float2bfloat16(v.y);
    __nv_bfloat16 h2 = __float2bfloat16(v.z);
    __nv_bfloat16 h3 = __float2bfloat16(v.w);
    __nv_bfloat16 l0 = __float2bfloat16(v.x - __bfloat162float(h0));
    __nv_bfloat16 l1 = __float2bfloat16(v.y - __bfloat162float(h1));
    __nv_bfloat16 l2 = __float2bfloat16(v.z - __bfloat162float(h2));
    __nv_bfloat16 l3 = __float2bfloat16(v.w - __bfloat162float(h3));
    hi.x = pack_bf16(h0, h1); hi.y = pack_bf16(h2, h3);
    lo.x = pack_bf16(l0, l1); lo.y = pack_bf16(l2, l3);
}
__device__ __forceinline__ void convert_to_slot(char* smem, int s, int ct,
                                                const float4* xr) {
#pragma unroll
    for (int q = 0; q < 4; ++q) {
        int idx = ct + (q << 7);
        int row = idx >> 4, c4 = idx & 15;
        uint32_t off = (uint32_t)row * ROWB + c4 * 8;
        uint2 hi, lo; cvt_pack(xr[q], hi, lo);
        *reinterpret_cast<uint2*>(smem + XBUF(s) + off)        = hi;
        *reinterpret_cast<uint2*>(smem + XBUF(s) + 4608 + off) = lo;
    }
}

// ============================================================================
// Bulk-synchronous double-buffered kernel. 1 CTA / batch, 256 threads.
// ONE __syncthreads() per tile. Phase i:
//   producers (tid>=128): GEMM x-slot i&1 -> ff-slot i&1  (R5 tiling)
//   consumers (tid<128) : LDS+scan ff-slot (i-1)&1, convert x(i+1) -> (i+1)&1
// ============================================================================
__global__ void __launch_bounds__(256, 2)
snn_encoder_kernel(const float* __restrict__ x, const float* __restrict__ W,
                   const float* __restrict__ bvec, float* __restrict__ out) {
    extern __shared__ char smem[];
    const uint32_t sb = smem_to_u32(smem);
    const int tid = threadIdx.x;
    const int b   = blockIdx.x;
    const float* xb = x + (size_t)b * T_DIM * K_DIM;

    // ---- Cooperative W convert: (2.5*W) fp32 -> bf16 hi/lo (hi aliases ff)
    {
        const float4* w4 = reinterpret_cast<const float4*>(W);
#pragma unroll
        for (int q = 0; q < 8; ++q) {
            int idx = tid + (q << 8);
            float4 v = __ldg(&w4[idx]);
            v.x *= 2.5f; v.y *= 2.5f; v.z *= 2.5f; v.w *= 2.5f;
            int row = idx >> 4, c4 = idx & 15;
            uint32_t off = (uint32_t)row * ROWB + c4 * 8;
            uint2 hi, lo; cvt_pack(v, hi, lo);
            *reinterpret_cast<uint2*>(smem + SMEM_W_HI + off) = hi;
            *reinterpret_cast<uint2*>(smem + SMEM_W_LO + off) = lo;
        }
    }
    __syncthreads();

    const bool is_prod = (tid >= 128);
    const int  lane = tid & 31;

    // ---------------- per-role persistent state ----------------
    // producer
    uint32_t Ahi[2][4][4];
    uint32_t aW_lo = 0, b_off = 0;
    float bias0[2], bias1[2];
    int r0 = lane >> 2, c0 = 2 * (lane & 3);
    // consumer
    float4 xr[4];
    float z = -1.0f;                 // 0.9*y_{-1} - 1.25*th_{-1} (mem=spk=0)
    float* outp = nullptr;

    if (is_prod) {
        const int pt = tid - 128;
        const int pw = pt >> 5;                  // heads [32pw, 32pw+32)
        const int j  = lane >> 3;
        const uint32_t a_off = (uint32_t)(((j & 1) * 8 + (lane & 7)) * WSTR + ((j >> 1) * 8)) * 2;
        b_off = (uint32_t)(((j >> 1) * 8 + (lane & 7)) * WSTR + ((j & 1) * 8)) * 2;
        aW_lo = sb + SMEM_W_LO + (uint32_t)(pw * 32) * ROWB + a_off;

        const uint32_t aW_hi = sb + SMEM_W_HI + (uint32_t)(pw * 32) * ROWB + a_off;
#pragma unroll
        for (int mt = 0; mt < 2; ++mt)
#pragma unroll
            for (int ks = 0; ks < 4; ++ks)
                ldm_x4(Ahi[mt][ks], aW_hi + (uint32_t)mt * 16 * ROWB + ks * 32);
        // all producer warps hoisted before any ff STS overwrites W_hi
        asm volatile("bar.sync 13, 128;" ::: "memory");

#pragma unroll
        for (int mt = 0; mt < 2; ++mt) {
            bias0[mt] = fmaf(__ldg(&bvec[pw * 32 + mt * 16 + r0]), 2.5f, -1.5f);
            bias1[mt] = fmaf(__ldg(&bvec[pw * 32 + mt * 16 + r0 + 8]), 2.5f, -1.5f);
        }
    } else {
        outp = out + (size_t)b * T_DIM * H_DIM + tid;
        // prologue: convert x(0) into slot 0; prefetch x(1) regs
        const float4* x4 = reinterpret_cast<const float4*>(xb);
#pragma unroll
        for (int q = 0; q < 4; ++q) xr[q] = __ldg(&x4[tid + (q << 7)]);
        convert_to_slot(smem, 0, tid, xr);
        x4 = reinterpret_cast<const float4*>(xb + (size_t)TILE_T * K_DIM);
#pragma unroll
        for (int q = 0; q < 4; ++q) xr[q] = __ldg(&x4[tid + (q << 7)]);
    }
    __syncthreads();                             // x(0) visible to producers

    // ==================== main loop: ONE sync per tile ====================
#pragma unroll 2
    for (int i = 0; i < N_TILES; ++i) {
        const int s = i & 1;

        if (is_prod) {
            // ---- GEMM tile i from x slot s (R5 tiling, 96 HMMA, 8 chains)
            float d[2][4][4];
#pragma unroll
            for (int mt = 0; mt < 2; ++mt)
#pragma unroll
                for (int nt = 0; nt < 4; ++nt) {
                    d[mt][nt][0] = bias0[mt]; d[mt][nt][1] = bias0[mt];
                    d[mt][nt][2] = bias1[mt]; d[mt][nt][3] = bias1[mt];
                }
            const uint32_t bX_hi = sb + XBUF(s) + b_off;
            const uint32_t bX_lo = bX_hi + 4608;
#pragma unroll
            for (int ks = 0; ks < 4; ++ks) {
                uint32_t alo[2][4], bh[2][4], bl[2][4];
                ldm_x4(alo[0], aW_lo + ks * 32);
                ldm_x4(alo[1], aW_lo + 16 * ROWB + ks * 32);
                ldm_x4(bh[0], bX_hi + ks * 32);
                ldm_x4(bh[1], bX_hi + 16 * ROWB + ks * 32);
                ldm_x4(bl[0], bX_lo + ks * 32);
                ldm_x4(bl[1], bX_lo + 16 * ROWB + ks * 32);
#pragma unroll
                for (int mt = 0; mt < 2; ++mt)
#pragma unroll
                    for (int nt = 0; nt < 4; ++nt) {
                        const uint32_t* bhp = &bh[nt >> 1][(nt & 1) * 2];
                        const uint32_t* blp = &bl[nt >> 1][(nt & 1) * 2];
                        mma_bf16(d[mt][nt], Ahi[mt][ks], bhp);
                        mma_bf16(d[mt][nt], Ahi[mt][ks], blp);
                        mma_bf16(d[mt][nt], alo[mt], bhp);
                    }
            }
            // ---- store ff tile into slot s, [t][h] stride 132
            {
                const int pw = (tid - 128) >> 5;
                float* ffp = reinterpret_cast<float*>(smem + FFB(s));
                const int baser = pw * 32 + r0;
#pragma unroll
                for (int mt = 0; mt < 2; ++mt) {
                    const int row = baser + mt * 16;
#pragma unroll
                    for (int nt = 0; nt < 4; ++nt) {
                        const int col = nt * 8 + c0;
                        ffp[col * FF_STR + row]           = d[mt][nt][0];
                        ffp[(col + 1) * FF_STR + row]     = d[mt][nt][1];
                        ffp[col * FF_STR + row + 8]       = d[mt][nt][2];
                        ffp[(col + 1) * FF_STR + row + 8] = d[mt][nt][3];
                    }
                }
            }
        } else {
            // ---- scan tile i-1 from ff slot s^1 (written in phase i-1)
            float g[TILE_T];
            if (i >= 1) {
                const float* fp = reinterpret_cast<const float*>(smem + FFB(s ^ 1)) + tid;
#pragma unroll
                for (int t = 0; t < TILE_T; ++t) g[t] = fp[t * FF_STR];
            }
            // ---- convert x(i+1) into slot s^1 (regs prefetched last phase)
            if (i + 1 < N_TILES) {
                convert_to_slot(smem, s ^ 1, tid, xr);
            }
            // ---- prefetch x(i+2) into regs
            if (i + 2 < N_TILES) {
                const float4* x4 = reinterpret_cast<const float4*>(
                    xb + (size_t)(i + 2) * TILE_T * K_DIM);
#pragma unroll
                for (int q = 0; q < 4; ++q) xr[q] = __ldg(&x4[tid + (q << 7)]);
            }
            // ---- run the scan (long latency chain)
            if (i >= 1) {
                float* po = outp + (size_t)(i - 1) * TILE_T * H_DIM;
                float y = z + g[0];
#pragma unroll
                for (int t = 0; t < TILE_T; ++t) {
                    float th = tanhf_approx(y);        // MUFU (critical path)
                    float gn = (t < TILE_T - 1) ? g[t + 1] : 0.0f;
                    float a  = fmaf(0.9f, y, gn);      // parallel with tanh
                    y = fmaf(th, -1.25f, a);           // y_{t+1} (z at t=31)
                    float spk = fmaf(th, 0.5f, 0.5f);  // off critical path
                    po[(size_t)t * H_DIM] = spk;
                }
                z = y;
            }
        }
        __syncthreads();                         // the ONLY per-tile barrier
    }

    // ==================== epilogue: scan last tile ====================
    if (!is_prod) {
        const int s = (N_TILES - 1) & 1;
        const float* fp = reinterpret_cast<const float*>(smem + FFB(s)) + tid;
        float g[TILE_T];
#pragma unroll
        for (int t = 0; t < TILE_T; ++t) g[t] = fp[t * FF_STR];
        float* po = outp + (size_t)(N_TILES - 1) * TILE_T * H_DIM;
        float y = z + g[0];
#pragma unroll
        for (int t = 0; t < TILE_T; ++t) {
            float th = tanhf_approx(y);
            float gn = (t < TILE_T - 1) ? g[t + 1] : 0.0f;
            float a  = fmaf(0.9f, y, gn);
            y = fmaf(th, -1.25f, a);
            float spk = fmaf(th, 0.5f, 0.5f);
            po[(size_t)t * H_DIM] = spk;
        }
    }
}

// ============================================================================
// Launch. Inputs: x [256,2048,64] f32, W [128,64] f32, b [128] f32 -> out f32
// ============================================================================
extern "C" void kernel_launch(void* const* d_in, const int* in_sizes, int n_in,
                              void* d_out, int out_size) {
    const float* x = (const float*)d_in[0];
    const float* W = (const float*)d_in[1];
    const float* b = (const float*)d_in[2];
    float* out = (float*)d_out;

    cudaFuncSetAttribute(snn_encoder_kernel,
                         cudaFuncAttributeMaxDynamicSharedMemorySize, SMEM_TOTAL);
    snn_encoder_kernel<<<B_DIM, 256, SMEM_TOTAL>>>(x, W, b, out);
}

// round 11
// speedup vs baseline: 1.0283x; 1.0283x over previous
#include <cuda_runtime.h>
#include <cuda_bf16.h>
#include <cstdint>

// ============================================================================
// Problem constants
// ============================================================================
#define B_DIM   256
#define T_DIM   2048
#define K_DIM   64
#define H_DIM   128
#define H_HALF  64
#define TILE_T  32
#define N_TILES (T_DIM / TILE_T)   // 64

// Scan: y_t = 0.9*y_{t-1} - 1.25*th_{t-1} + g_t, th = tanh(y), spk = .5th+.5
// g = 2.5*ff - 1.5  (2.5 folded into W, bias' = 2.5b - 1.5)

// ============================================================================
// SMEM layout (bytes) — 53760 total, 4 CTAs/SM
//   [0, 18432)       x ring: 2 slots x 9216 (hi 4608 + lo 4608), 32x144B rows
//   [18432, 27648)   W_lo persistent (64 rows x 144 B, this CTA's head-half)
//   [27648, 53760)   ff ring: 3 slots x 8704 ([t][h] stride 68 floats)
//   W_hi (init only) aliases ff region at 27648 (9216 B, spans slots 0-1).
// ============================================================================
#define WSTR      72
#define ROWB      144
#define XBUF(s)   ((s) * 9216)
#define SMEM_W_LO 18432
#define SMEM_FF   27648
#define FFB(s)    (SMEM_FF + (s) * 8704)
#define FF_STR    68
#define SMEM_W_HI 27648
#define SMEM_TOTAL 53760

// Named barriers (128 = 64 producers + 64 consumers):
//   FFREADY(s)=1+s (s 0..2), FFFREE(s)=4+s, XREADY(s)=7+s (s 0..1),
//   XFREE(s)=9+s, 11 = producer-only (64) W_hi hoist guard
#define BAR_SYNC(id)   asm volatile("bar.sync %0, 128;"   :: "r"(id) : "memory")
#define BAR_ARRIVE(id) asm volatile("bar.arrive %0, 128;" :: "r"(id) : "memory")

// ============================================================================
// Helpers
// ============================================================================
__device__ __forceinline__ uint32_t smem_to_u32(const void* p) {
    uint32_t a;
    asm("{ .reg .u64 t; cvta.to.shared.u64 t, %1; cvt.u32.u64 %0, t; }"
        : "=r"(a) : "l"(p));
    return a;
}
__device__ __forceinline__ float tanhf_approx(float x) {
    float y; asm("tanh.approx.f32 %0, %1;" : "=f"(y) : "f"(x)); return y;
}
__device__ __forceinline__ void ldm_x4(uint32_t* r, uint32_t addr) {
    asm volatile("ldmatrix.sync.aligned.m8n8.x4.shared.b16 {%0,%1,%2,%3}, [%4];"
        : "=r"(r[0]), "=r"(r[1]), "=r"(r[2]), "=r"(r[3]) : "r"(addr));
}
__device__ __forceinline__ void mma_bf16(float* d, const uint32_t* a, const uint32_t* b) {
    asm volatile(
        "mma.sync.aligned.m16n8k16.row.col.f32.bf16.bf16.f32 "
        "{%0,%1,%2,%3},{%4,%5,%6,%7},{%8,%9},{%0,%1,%2,%3};"
        : "+f"(d[0]), "+f"(d[1]), "+f"(d[2]), "+f"(d[3])
        : "r"(a[0]), "r"(a[1]), "r"(a[2]), "r"(a[3]), "r"(b[0]), "r"(b[1]));
}
__device__ __forceinline__ uint32_t pack_bf16(__nv_bfloat16 a, __nv_bfloat16 b) {
    return ((uint32_t)__bfloat16_as_ushort(b) << 16) | __bfloat16_as_ushort(a);
}
__device__ __forceinline__ void cvt_pack(float4 v, uint2& hi, uint2& lo) {
    __nv_bfloat16 h0 = __float2bfloat16(v.x);
    __nv_bfloat16 h1 = __float2bfloat16(v.y);
    __nv_bfloat16 h2 = __float2bfloat16(v.z);
    __nv_bfloat16 h3 = __float2bfloat16(v.w);
    __nv_bfloat16 l0 = __float2bfloat16(v.x - __bfloat162float(h0));
    __nv_bfloat16 l1 = __float2bfloat16(v.y - __bfloat162float(h1));
    __nv_bfloat16 l2 = __float2bfloat16(v.z - __bfloat162float(h2));
    __nv_bfloat16 l3 = __float2bfloat16(v.w - __bfloat162float(h3));
    hi.x = pack_bf16(h0, h1); hi.y = pack_bf16(h2, h3);
    lo.x = pack_bf16(l0, l1); lo.y = pack_bf16(l2, l3);
}
// consumer-side: 8 float4 per thread (64 threads cover 32x64 tile)
__device__ __forceinline__ void convert_to_slot(char* smem, int s, int ct,
                                                const float4* xr) {
#pragma unroll
    for (int q = 0; q < 8; ++q) {
        int idx = ct + (q << 6);
        int row = idx >> 4, c4 = idx & 15;
        uint32_t off = (uint32_t)row * ROWB + c4 * 8;
        uint2 hi, lo; cvt_pack(xr[q], hi, lo);
        *reinterpret_cast<uint2*>(smem + XBUF(s) + off)        = hi;
        *reinterpret_cast<uint2*>(smem + XBUF(s) + 4608 + off) = lo;
    }
}

// ============================================================================
// Head-split warp-specialized kernel. Grid 512 = (batch, head-half).
// 128 threads: tid 0..63 consumers (thread = head in half, tanh scan + x feed)
//              tid 64..127 producers (2 warps, R5 GEMM tiling per warp)
// ============================================================================
__global__ void __launch_bounds__(128, 4)
snn_encoder_kernel(const float* __restrict__ x, const float* __restrict__ W,
                   const float* __restrict__ bvec, float* __restrict__ out) {
    extern __shared__ char smem[];
    const uint32_t sb = smem_to_u32(smem);
    const int tid = threadIdx.x;
    const int bx  = blockIdx.x;
    const int b   = bx >> 1;
    const int hh  = bx & 1;                      // head-half
    const float* xb = x + (size_t)b * T_DIM * K_DIM;

    // ---- W convert: this CTA's 64 rows of (2.5*W) -> bf16 hi/lo
    {
        const float4* w4 = reinterpret_cast<const float4*>(W + (size_t)hh * H_HALF * K_DIM);
#pragma unroll
        for (int q = 0; q < 8; ++q) {
            int idx = tid + (q << 7);            // 1024 float4
            float4 v = __ldg(&w4[idx]);
            v.x *= 2.5f; v.y *= 2.5f; v.z *= 2.5f; v.w *= 2.5f;
            int row = idx >> 4, c4 = idx & 15;
            uint32_t off = (uint32_t)row * ROWB + c4 * 8;
            uint2 hi, lo; cvt_pack(v, hi, lo);
            *reinterpret_cast<uint2*>(smem + SMEM_W_HI + off) = hi;
            *reinterpret_cast<uint2*>(smem + SMEM_W_LO + off) = lo;
        }
    }
    __syncthreads();

    if (tid >= 64) {
        // ==================== PRODUCERS (2 warps, R5 tiling) ====================
        const int pt   = tid - 64;               // 0..63
        const int lane = pt & 31;
        const int pw   = pt >> 5;                // local heads [32pw, 32pw+32)
        const int j    = lane >> 3;

        const uint32_t a_off = (uint32_t)(((j & 1) * 8 + (lane & 7)) * WSTR + ((j >> 1) * 8)) * 2;
        const uint32_t b_off = (uint32_t)(((j >> 1) * 8 + (lane & 7)) * WSTR + ((j & 1) * 8)) * 2;
        const uint32_t aW_lo = sb + SMEM_W_LO + (uint32_t)(pw * 32) * ROWB + a_off;

        // hoist W_hi fragments (ff ring aliases this region afterwards)
        uint32_t Ahi[2][4][4];
        {
            const uint32_t aW_hi = sb + SMEM_W_HI + (uint32_t)(pw * 32) * ROWB + a_off;
#pragma unroll
            for (int mt = 0; mt < 2; ++mt)
#pragma unroll
                for (int ks = 0; ks < 4; ++ks)
                    ldm_x4(Ahi[mt][ks], aW_hi + (uint32_t)mt * 16 * ROWB + ks * 32);
        }
        asm volatile("bar.sync 11, 64;" ::: "memory");

        // bias' = 2.5*b - 1.5 folded into accumulator init
        const int r0 = lane >> 2;
        const int c0 = 2 * (lane & 3);
        float bias0[2], bias1[2];
#pragma unroll
        for (int mt = 0; mt < 2; ++mt) {
            bias0[mt] = fmaf(__ldg(&bvec[hh * H_HALF + pw * 32 + mt * 16 + r0]), 2.5f, -1.5f);
            bias1[mt] = fmaf(__ldg(&bvec[hh * H_HALF + pw * 32 + mt * 16 + r0 + 8]), 2.5f, -1.5f);
        }

        int sf = 0;
        for (int i = 0; i < N_TILES; ++i) {
            const int sx = i & 1;
            BAR_SYNC(7 + sx);                    // wait x tile i converted

            float d[2][4][4];
#pragma unroll
            for (int mt = 0; mt < 2; ++mt)
#pragma unroll
                for (int nt = 0; nt < 4; ++nt) {
                    d[mt][nt][0] = bias0[mt]; d[mt][nt][1] = bias0[mt];
                    d[mt][nt][2] = bias1[mt]; d[mt][nt][3] = bias1[mt];
                }
            const uint32_t bX_hi = sb + XBUF(sx) + b_off;
            const uint32_t bX_lo = bX_hi + 4608;
#pragma unroll
            for (int ks = 0; ks < 4; ++ks) {
                uint32_t alo[2][4], bh[2][4], bl[2][4];
                ldm_x4(alo[0], aW_lo + ks * 32);
                ldm_x4(alo[1], aW_lo + 16 * ROWB + ks * 32);
                ldm_x4(bh[0], bX_hi + ks * 32);
                ldm_x4(bh[1], bX_hi + 16 * ROWB + ks * 32);
                ldm_x4(bl[0], bX_lo + ks * 32);
                ldm_x4(bl[1], bX_lo + 16 * ROWB + ks * 32);
#pragma unroll
                for (int mt = 0; mt < 2; ++mt)
#pragma unroll
                    for (int nt = 0; nt < 4; ++nt) {
                        const uint32_t* bhp = &bh[nt >> 1][(nt & 1) * 2];
                        const uint32_t* blp = &bl[nt >> 1][(nt & 1) * 2];
                        mma_bf16(d[mt][nt], Ahi[mt][ks], bhp);
                        mma_bf16(d[mt][nt], Ahi[mt][ks], blp);
                        mma_bf16(d[mt][nt], alo[mt], bhp);
                    }
            }
            BAR_ARRIVE(9 + sx);                  // x slot free (LDSM done)

            if (i >= 3) BAR_SYNC(4 + sf);        // wait ff slot free

            // store ff tile, layout [t][h_local], stride 68 (conflict-free)
            {
                float* ffp = reinterpret_cast<float*>(smem + FFB(sf));
                const int baser = pw * 32 + r0;
#pragma unroll
                for (int mt = 0; mt < 2; ++mt) {
                    const int row = baser + mt * 16;
#pragma unroll
                    for (int nt = 0; nt < 4; ++nt) {
                        const int col = nt * 8 + c0;
                        ffp[col * FF_STR + row]           = d[mt][nt][0];
                        ffp[(col + 1) * FF_STR + row]     = d[mt][nt][1];
                        ffp[col * FF_STR + row + 8]       = d[mt][nt][2];
                        ffp[(col + 1) * FF_STR + row + 8] = d[mt][nt][3];
                    }
                }
            }
            BAR_ARRIVE(1 + sf);                  // ff tile ready
            if (++sf == 3) sf = 0;
        }
    } else {
        // ==================== CONSUMERS (scan + x feed) ====================
        const int h  = tid;                      // local head 0..63
        const int ct = tid;
        float* outp = out + (size_t)b * T_DIM * H_DIM + hh * H_HALF + h;

        // prologue: convert x tiles 0,1 into slots 0,1; prefetch tile 2 regs
        float4 xr[8];
        {
            const float4* x4 = reinterpret_cast<const float4*>(xb);
#pragma unroll
            for (int q = 0; q < 8; ++q) xr[q] = __ldg(&x4[ct + (q << 6)]);
            convert_to_slot(smem, 0, ct, xr);
            BAR_ARRIVE(7 + 0);
            x4 = reinterpret_cast<const float4*>(xb + (size_t)TILE_T * K_DIM);
#pragma unroll
            for (int q = 0; q < 8; ++q) xr[q] = __ldg(&x4[ct + (q << 6)]);
            convert_to_slot(smem, 1, ct, xr);
            BAR_ARRIVE(7 + 1);
            x4 = reinterpret_cast<const float4*>(xb + (size_t)2 * TILE_T * K_DIM);
#pragma unroll
            for (int q = 0; q < 8; ++q) xr[q] = __ldg(&x4[ct + (q << 6)]);
        }

        // scan state: z = 0.9*y_{-1} - 1.25*th_{-1} = -1.0 (mem=0, spk=0)
        float z = -1.0f;
        int sf = 0;

        for (int i = 0; i < N_TILES; ++i) {
            // convert tile i+2 into slot i&1 (regs loaded last iter)
            if (i + 2 < N_TILES) {
                const int sx = i & 1;
                BAR_SYNC(9 + sx);                // producer done LDSM tile i
                convert_to_slot(smem, sx, ct, xr);
                BAR_ARRIVE(7 + sx);
            }
            // prefetch tile i+3 regs
            if (i + 3 < N_TILES) {
                const float4* x4 = reinterpret_cast<const float4*>(
                    xb + (size_t)(i + 3) * TILE_T * K_DIM);
#pragma unroll
                for (int q = 0; q < 8; ++q) xr[q] = __ldg(&x4[ct + (q << 6)]);
            }

            BAR_SYNC(1 + sf);                    // wait ff tile i
            const float* fp = reinterpret_cast<const float*>(smem + FFB(sf)) + h;
            float g[TILE_T];
#pragma unroll
            for (int t = 0; t < TILE_T; ++t) g[t] = fp[t * FF_STR];
            BAR_ARRIVE(4 + sf);                  // free ff slot immediately
            if (++sf == 3) sf = 0;

            float* po = outp + (size_t)i * TILE_T * H_DIM;
            float y = z + g[0];
#pragma unroll
            for (int t = 0; t < TILE_T; ++t) {
                float th = tanhf_approx(y);          // MUFU (critical path)
                float gn = (t < TILE_T - 1) ? g[t + 1] : 0.0f;
                float a  = fmaf(0.9f, y, gn);        // parallel with tanh
                y = fmaf(th, -1.25f, a);             // y_{t+1} (or z at t=31)
                float spk = fmaf(th, 0.5f, 0.5f);    // off critical path
                po[(size_t)t * H_DIM] = spk;
            }
            z = y;                               // carry partial to next tile
        }
    }
}

// ============================================================================
// Launch. Inputs: x [256,2048,64] f32, W [128,64] f32, b [128] f32 -> out f32
// ============================================================================
extern "C" void kernel_launch(void* const* d_in, const int* in_sizes, int n_in,
                              void* d_out, int out_size) {
    const float* x = (const float*)d_in[0];
    const float* W = (const float*)d_in[1];
    const float* b = (const float*)d_in[2];
    float* out = (float*)d_out;

    cudaFuncSetAttribute(snn_encoder_kernel,
                         cudaFuncAttributeMaxDynamicSharedMemorySize, SMEM_TOTAL);
    snn_encoder_kernel<<<B_DIM * 2, 128, SMEM_TOTAL>>>(x, W, b, out);
}

// round 12
// speedup vs baseline: 1.4140x; 1.3751x over previous
#include <cuda_runtime.h>
#include <cuda_fp16.h>
#include <cstdint>

// ============================================================================
// Problem constants
// ============================================================================
#define B_DIM   256
#define T_DIM   2048
#define K_DIM   64
#define H_DIM   128
#define TILE_T  32
#define N_TILES (T_DIM / TILE_T)   // 64

// Scan: y_t = 0.9*y_{t-1} - 1.25*th_{t-1} + g_t, th = tanh(y), spk = .5th+.5
// g = 2.5*ff - 1.5  (2.5 folded into W, bias' = 2.5b - 1.5)
// GEMM: 2-term fp16 split  ff ~= wh*xh + wh*xl,  xl = fp16(x - xh)

// ============================================================================
// SMEM layout (bytes) — 78336 total (2 CTAs/SM)
//   [0, 27648)       x ring: 3 slots x 9216 (fp16 hi 4608 + fp16 lo 4608)
//   [27648, 78336)   ff ring: 3 slots x 16896 ([t][h] stride 132 floats)
//   W_hi (init only) aliases ff region at 27648 (128 x 144 B = 18432).
// ============================================================================
#define WSTR      72
#define ROWB      144
#define XBUF(s)   ((s) * 9216)
#define SMEM_FF   27648
#define FFB(s)    (SMEM_FF + (s) * 16896)
#define FF_STR    132
#define SMEM_W_HI 27648
#define SMEM_TOTAL 78336

// Named barriers (256 threads = 128 producers + 128 consumers):
//   FFREADY(s)=1+s, FFFREE(s)=4+s, XREADY(s)=7+s, XFREE(s)=10+s,
//   13 = producer-only (128) W_hi hoist guard
#define BAR_SYNC(id)   asm volatile("bar.sync %0, 256;"   :: "r"(id) : "memory")
#define BAR_ARRIVE(id) asm volatile("bar.arrive %0, 256;" :: "r"(id) : "memory")

// ============================================================================
// Helpers
// ============================================================================
__device__ __forceinline__ uint32_t smem_to_u32(const void* p) {
    uint32_t a;
    asm("{ .reg .u64 t; cvta.to.shared.u64 t, %1; cvt.u32.u64 %0, t; }"
        : "=r"(a) : "l"(p));
    return a;
}
__device__ __forceinline__ float tanhf_approx(float x) {
    float y; asm("tanh.approx.f32 %0, %1;" : "=f"(y) : "f"(x)); return y;
}
__device__ __forceinline__ void ldm_x4(uint32_t* r, uint32_t addr) {
    asm volatile("ldmatrix.sync.aligned.m8n8.x4.shared.b16 {%0,%1,%2,%3}, [%4];"
        : "=r"(r[0]), "=r"(r[1]), "=r"(r[2]), "=r"(r[3]) : "r"(addr));
}
__device__ __forceinline__ void mma_f16(float* d, const uint32_t* a, const uint32_t* b) {
    asm volatile(
        "mma.sync.aligned.m16n8k16.row.col.f32.f16.f16.f32 "
        "{%0,%1,%2,%3},{%4,%5,%6,%7},{%8,%9},{%0,%1,%2,%3};"
        : "+f"(d[0]), "+f"(d[1]), "+f"(d[2]), "+f"(d[3])
        : "r"(a[0]), "r"(a[1]), "r"(a[2]), "r"(a[3]), "r"(b[0]), "r"(b[1]));
}
__device__ __forceinline__ uint32_t pack_h2(__half a, __half b) {
    return ((uint32_t)__half_as_ushort(b) << 16) | __half_as_ushort(a);
}
// fp16 2-term split: hi = fp16(v), lo = fp16(v - hi)
__device__ __forceinline__ void cvt_pack_f16(float4 v, uint2& hi, uint2& lo) {
    __half h0 = __float2half_rn(v.x);
    __half h1 = __float2half_rn(v.y);
    __half h2 = __float2half_rn(v.z);
    __half h3 = __float2half_rn(v.w);
    __half l0 = __float2half_rn(v.x - __half2float(h0));
    __half l1 = __float2half_rn(v.y - __half2float(h1));
    __half l2 = __float2half_rn(v.z - __half2float(h2));
    __half l3 = __float2half_rn(v.w - __half2float(h3));
    hi.x = pack_h2(h0, h1); hi.y = pack_h2(h2, h3);
    lo.x = pack_h2(l0, l1); lo.y = pack_h2(l2, l3);
}
// consumer-side: convert xr regs -> x ring slot s (hi + lo fp16 planes)
__device__ __forceinline__ void convert_to_slot(char* smem, int s, int ct,
                                                const float4* xr) {
#pragma unroll
    for (int q = 0; q < 4; ++q) {
        int idx = ct + (q << 7);
        int row = idx >> 4, c4 = idx & 15;
        uint32_t off = (uint32_t)row * ROWB + c4 * 8;
        uint2 hi, lo; cvt_pack_f16(xr[q], hi, lo);
        *reinterpret_cast<uint2*>(smem + XBUF(s) + off)        = hi;
        *reinterpret_cast<uint2*>(smem + XBUF(s) + 4608 + off) = lo;
    }
}

// ============================================================================
// Warp-specialized kernel (R5 skeleton). 1 CTA / batch, 256 threads.
//   tid 0..127  : consumers — tanh scan (thread = head) + x load/convert
//   tid 128..255: producers — 2-term fp16 GEMM (A = wh in regs, 64 HMMA/tile)
// ============================================================================
__global__ void __launch_bounds__(256, 2)
snn_encoder_kernel(const float* __restrict__ x, const float* __restrict__ W,
                   const float* __restrict__ bvec, float* __restrict__ out) {
    extern __shared__ char smem[];
    const uint32_t sb = smem_to_u32(smem);
    const int tid = threadIdx.x;
    const int b   = blockIdx.x;
    const float* xb = x + (size_t)b * T_DIM * K_DIM;

    // ---- Cooperative W convert: (2.5*W) fp32 -> fp16 hi only (aliases ff)
    {
        const float4* w4 = reinterpret_cast<const float4*>(W);
#pragma unroll
        for (int q = 0; q < 8; ++q) {
            int idx = tid + (q << 8);            // 2048 float4
            float4 v = __ldg(&w4[idx]);
            v.x *= 2.5f; v.y *= 2.5f; v.z *= 2.5f; v.w *= 2.5f;
            int row = idx >> 4, c4 = idx & 15;
            uint32_t off = (uint32_t)row * ROWB + c4 * 8;
            __half h0 = __float2half_rn(v.x);
            __half h1 = __float2half_rn(v.y);
            __half h2 = __float2half_rn(v.z);
            __half h3 = __float2half_rn(v.w);
            uint2 hi;
            hi.x = pack_h2(h0, h1); hi.y = pack_h2(h2, h3);
            *reinterpret_cast<uint2*>(smem + SMEM_W_HI + off) = hi;
        }
    }
    __syncthreads();

    if (tid >= 128) {
        // ==================== PRODUCERS ====================
        const int pt   = tid - 128;
        const int lane = pt & 31;
        const int pw   = pt >> 5;                // heads [32pw, 32pw+32)
        const int j    = lane >> 3;

        const uint32_t a_off = (uint32_t)(((j & 1) * 8 + (lane & 7)) * WSTR + ((j >> 1) * 8)) * 2;
        const uint32_t b_off = (uint32_t)(((j >> 1) * 8 + (lane & 7)) * WSTR + ((j & 1) * 8)) * 2;

        // hoist W_hi fragments into registers (ff ring aliases W_hi after)
        uint32_t Ahi[2][4][4];
        {
            const uint32_t aW_hi = sb + SMEM_W_HI + (uint32_t)(pw * 32) * ROWB + a_off;
#pragma unroll
            for (int mt = 0; mt < 2; ++mt)
#pragma unroll
                for (int ks = 0; ks < 4; ++ks)
                    ldm_x4(Ahi[mt][ks], aW_hi + (uint32_t)mt * 16 * ROWB + ks * 32);
        }
        // all producers hoisted before any ff STS overwrites W_hi
        asm volatile("bar.sync 13, 128;" ::: "memory");

        // bias' = 2.5*b - 1.5 folded into accumulator init
        const int r0 = lane >> 2;
        const int c0 = 2 * (lane & 3);
        float bias0[2], bias1[2];
#pragma unroll
        for (int mt = 0; mt < 2; ++mt) {
            bias0[mt] = fmaf(__ldg(&bvec[pw * 32 + mt * 16 + r0]), 2.5f, -1.5f);
            bias1[mt] = fmaf(__ldg(&bvec[pw * 32 + mt * 16 + r0 + 8]), 2.5f, -1.5f);
        }

        int sx = 0, sf = 0;
        for (int i = 0; i < N_TILES; ++i) {
            BAR_SYNC(7 + sx);                    // wait x tile i converted

            float d[2][4][4];
#pragma unroll
            for (int mt = 0; mt < 2; ++mt)
#pragma unroll
                for (int nt = 0; nt < 4; ++nt) {
                    d[mt][nt][0] = bias0[mt]; d[mt][nt][1] = bias0[mt];
                    d[mt][nt][2] = bias1[mt]; d[mt][nt][3] = bias1[mt];
                }
            const uint32_t bX_hi = sb + XBUF(sx) + b_off;
            const uint32_t bX_lo = bX_hi + 4608;
#pragma unroll
            for (int ks = 0; ks < 4; ++ks) {
                uint32_t bh[2][4], bl[2][4];
                ldm_x4(bh[0], bX_hi + ks * 32);
                ldm_x4(bh[1], bX_hi + 16 * ROWB + ks * 32);
                ldm_x4(bl[0], bX_lo + ks * 32);
                ldm_x4(bl[1], bX_lo + 16 * ROWB + ks * 32);
#pragma unroll
                for (int mt = 0; mt < 2; ++mt)
#pragma unroll
                    for (int nt = 0; nt < 4; ++nt) {
                        const uint32_t* bhp = &bh[nt >> 1][(nt & 1) * 2];
                        const uint32_t* blp = &bl[nt >> 1][(nt & 1) * 2];
                        mma_f16(d[mt][nt], Ahi[mt][ks], bhp);   // wh * xh
                        mma_f16(d[mt][nt], Ahi[mt][ks], blp);   // wh * xl
                    }
            }
            BAR_ARRIVE(10 + sx);                 // x slot free (LDSM done)

            if (i >= 3) BAR_SYNC(4 + sf);        // wait ff slot free

            // store ff tile, layout [t][h], stride 132 (conflict-free)
            {
                float* ffp = reinterpret_cast<float*>(smem + FFB(sf));
                const int baser = pw * 32 + r0;
#pragma unroll
                for (int mt = 0; mt < 2; ++mt) {
                    const int row = baser + mt * 16;
#pragma unroll
                    for (int nt = 0; nt < 4; ++nt) {
                        const int col = nt * 8 + c0;
                        ffp[col * FF_STR + row]           = d[mt][nt][0];
                        ffp[(col + 1) * FF_STR + row]     = d[mt][nt][1];
                        ffp[col * FF_STR + row + 8]       = d[mt][nt][2];
                        ffp[(col + 1) * FF_STR + row + 8] = d[mt][nt][3];
                    }
                }
            }
            BAR_ARRIVE(1 + sf);                  // ff tile ready

            if (++sx == 3) sx = 0;
            if (++sf == 3) sf = 0;
        }
    } else {
        // ==================== CONSUMERS (scan + x feed) ====================
        const int h  = tid;
        const int ct = tid;
        float* outp = out + (size_t)b * T_DIM * H_DIM + h;

        // prologue: convert x tiles 0,1 into slots 0,1; prefetch tile 2
        float4 xr[4];
        {
            const float4* x4 = reinterpret_cast<const float4*>(xb);
#pragma unroll
            for (int q = 0; q < 4; ++q) xr[q] = __ldg(&x4[ct + (q << 7)]);
            convert_to_slot(smem, 0, ct, xr);
            BAR_ARRIVE(7 + 0);
            x4 = reinterpret_cast<const float4*>(xb + (size_t)TILE_T * K_DIM);
#pragma unroll
            for (int q = 0; q < 4; ++q) xr[q] = __ldg(&x4[ct + (q << 7)]);
            convert_to_slot(smem, 1, ct, xr);
            BAR_ARRIVE(7 + 1);
            x4 = reinterpret_cast<const float4*>(xb + (size_t)2 * TILE_T * K_DIM);
#pragma unroll
            for (int q = 0; q < 4; ++q) xr[q] = __ldg(&x4[ct + (q << 7)]);
        }

        // scan state: z = 0.9*y_{-1} - 1.25*th_{-1} = -1.0 (mem=0, spk=0)
        float z = -1.0f;
        int sf = 0, sx = 2;                      // next convert slot = tile 2

        for (int i = 0; i < N_TILES; ++i) {
            // convert tile i+2 (regs loaded last iter), then prefetch i+3
            if (i + 2 < N_TILES) {
                if (i + 2 >= 3) BAR_SYNC(10 + sx);
                convert_to_slot(smem, sx, ct, xr);
                BAR_ARRIVE(7 + sx);
                if (++sx == 3) sx = 0;
            }
            if (i + 3 < N_TILES) {
                const float4* x4 = reinterpret_cast<const float4*>(
                    xb + (size_t)(i + 3) * TILE_T * K_DIM);
#pragma unroll
                for (int q = 0; q < 4; ++q) xr[q] = __ldg(&x4[ct + (q << 7)]);
            }

            BAR_SYNC(1 + sf);                    // wait ff tile i
            const float* fp = reinterpret_cast<const float*>(smem + FFB(sf)) + h;
            float g[TILE_T];
#pragma unroll
            for (int t = 0; t < TILE_T; ++t) g[t] = fp[t * FF_STR];
            BAR_ARRIVE(4 + sf);                  // free ff slot immediately
            if (++sf == 3) sf = 0;

            float* po = outp + (size_t)i * TILE_T * H_DIM;
            float y = z + g[0];
#pragma unroll
            for (int t = 0; t < TILE_T; ++t) {
                float th = tanhf_approx(y);          // MUFU (critical path)
                float gn = (t < TILE_T - 1) ? g[t + 1] : 0.0f;
                float a  = fmaf(0.9f, y, gn);        // parallel with tanh
                y = fmaf(th, -1.25f, a);             // y_{t+1} (or z at t=31)
                float spk = fmaf(th, 0.5f, 0.5f);    // off critical path
                po[(size_t)t * H_DIM] = spk;
            }
            z = y;                               // carry partial to next tile
        }
    }
}

// ============================================================================
// Launch. Inputs: x [256,2048,64] f32, W [128,64] f32, b [128] f32 -> out f32
// ============================================================================
extern "C" void kernel_launch(void* const* d_in, const int* in_sizes, int n_in,
                              void* d_out, int out_size) {
    const float* x = (const float*)d_in[0];
    const float* W = (const float*)d_in[1];
    const float* b = (const float*)d_in[2];
    float* out = (float*)d_out;

    cudaFuncSetAttribute(snn_encoder_kernel,
                         cudaFuncAttributeMaxDynamicSharedMemorySize, SMEM_TOTAL);
    snn_encoder_kernel<<<B_DIM, 256, SMEM_TOTAL>>>(x, W, b, out);
}